// round 15
// baseline (speedup 1.0000x reference)
#include <cuda_runtime.h>
#include <cuda_bf16.h>
#include <cuda_fp16.h>
#include <math_constants.h>
#include <cstddef>
#include <cstdint>

#define NB 8
#define NH 12
#define HD 64
#define DM 768
#define NSEQ 1024
#define NBH 96
#define SCALE 0.125f
#define EPSV 1e-6f
#define EPSN (1e-6f/1024.0f)
#define WOFF (2304*768)

__device__ float g_Q[NBH*NSEQ*HD];
__device__ float g_V[NBH*NSEQ*HD];
__device__ float g_relh[NBH*NSEQ*32];
__device__ float g_relw[NBH*NSEQ*32];
__device__ float g_vsum[NBH*HD];

__device__ __nv_bfloat16 g_Xhi[NB*NSEQ*DM], g_Xlo[NB*NSEQ*DM];
__device__ __nv_bfloat16 g_Whi[3072*DM],    g_Wlo[3072*DM];
__device__ __nv_bfloat16 g_Thi[NB*NSEQ*DM], g_Tlo[NB*NSEQ*DM];

// fp16 operands for flash (higher mantissa -> fewer MMA terms)
__device__ __half g_Qh16[NBH*NSEQ*HD];
__device__ __half g_Kh16[NBH*NSEQ*HD], g_Kl16[NBH*NSEQ*HD];
__device__ __half g_VTh16[NBH*HD*NSEQ], g_VTl16[NBH*HD*NSEQ];   // [bh][d][k]

#define MMA_BF16(d, a, b0, b1)                                             \
  asm volatile("mma.sync.aligned.m16n8k16.row.col.f32.bf16.bf16.f32 "      \
    "{%0,%1,%2,%3},{%4,%5,%6,%7},{%8,%9},{%0,%1,%2,%3};\n"                 \
    : "+f"(d[0]), "+f"(d[1]), "+f"(d[2]), "+f"(d[3])                       \
    : "r"(a[0]), "r"(a[1]), "r"(a[2]), "r"(a[3]), "r"(b0), "r"(b1))

#define MMA_F16(d, a, b0, b1)                                              \
  asm volatile("mma.sync.aligned.m16n8k16.row.col.f32.f16.f16.f32 "        \
    "{%0,%1,%2,%3},{%4,%5,%6,%7},{%8,%9},{%0,%1,%2,%3};\n"                 \
    : "+f"(d[0]), "+f"(d[1]), "+f"(d[2]), "+f"(d[3])                       \
    : "r"(a[0]), "r"(a[1]), "r"(a[2]), "r"(a[3]), "r"(b0), "r"(b1))

__device__ __forceinline__ uint32_t scvta(const void* p)
{
    return (uint32_t)__cvta_generic_to_shared(p);
}

__device__ __forceinline__ void ldsm_x4(uint32_t& r0, uint32_t& r1,
                                        uint32_t& r2, uint32_t& r3, uint32_t a)
{
    asm volatile("ldmatrix.sync.aligned.m8n8.x4.shared.b16 {%0,%1,%2,%3}, [%4];\n"
        : "=r"(r0), "=r"(r1), "=r"(r2), "=r"(r3) : "r"(a));
}

__device__ __forceinline__ void split2(float a, float b, uint32_t& hi, uint32_t& lo)
{
    __nv_bfloat162 h = __floats2bfloat162_rn(a, b);
    float ra = a - __bfloat162float(h.x);
    float rb = b - __bfloat162float(h.y);
    __nv_bfloat162 l = __floats2bfloat162_rn(ra, rb);
    hi = *(uint32_t*)&h;
    lo = *(uint32_t*)&l;
}

__device__ __forceinline__ void split2h(float a, float b, uint32_t& hi, uint32_t& lo)
{
    __half2 h = __floats2half2_rn(a, b);
    float ra = a - __low2float(h);
    float rb = b - __high2float(h);
    __half2 l = __floats2half2_rn(ra, rb);
    hi = *(uint32_t*)&h;
    lo = *(uint32_t*)&l;
}

__device__ __forceinline__ uint32_t pack_h2(float a, float b)
{
    __half2 h = __floats2half2_rn(a, b);
    return *(uint32_t*)&h;
}

__device__ __forceinline__ void cp16(void* smem, const void* gmem)
{
    uint32_t s = scvta(smem);
    asm volatile("cp.async.cg.shared.global [%0], [%1], 16;\n" :: "r"(s), "l"(gmem));
}
__device__ __forceinline__ void cp_commit()
{
    asm volatile("cp.async.commit_group;\n");
}
template<int N> __device__ __forceinline__ void cp_wait()
{
    asm volatile("cp.async.wait_group %0;\n" :: "n"(N));
}

// ---------------------------------------------------------------------------
__global__ void split_kernel(const float* __restrict__ src, int which, int n4)
{
    int i = blockIdx.x*256 + threadIdx.x;
    if (i >= n4) return;
    __nv_bfloat16 *hi, *lo;
    if (which == 0)      { hi = g_Xhi;        lo = g_Xlo; }
    else if (which == 1) { hi = g_Whi;        lo = g_Wlo; }
    else                 { hi = g_Whi + WOFF; lo = g_Wlo + WOFF; }
    float4 v = ((const float4*)src)[i];
    uint32_t h0, l0, h1, l1;
    split2(v.x, v.y, h0, l0);
    split2(v.z, v.w, h1, l1);
    ((uint32_t*)hi)[i*2]   = h0;
    ((uint32_t*)hi)[i*2+1] = h1;
    ((uint32_t*)lo)[i*2]   = l0;
    ((uint32_t*)lo)[i*2+1] = l1;
}

// ---------------------------------------------------------------------------
// Tensor-core GEMM (HMMA bf16 3-term), cp.async double-buffered, 2 CTAs/SM.
// mode 0 epilogue now emits fp16 flash operands.
// ---------------------------------------------------------------------------
#define GSTRIDE 5120
#define GEMM_SMEM_BYTES (2 * 4 * GSTRIDE * 2)

__global__ __launch_bounds__(256,2) void gemm_mma(
    const float* __restrict__ bias, float* __restrict__ out, int mode)
{
    extern __shared__ __nv_bfloat16 smg[];
    __nv_bfloat16* As = smg;
    __nv_bfloat16* Bs = smg + 2*2*GSTRIDE;
    const __nv_bfloat16* Ah = mode ? g_Thi : g_Xhi;
    const __nv_bfloat16* Al = mode ? g_Tlo : g_Xlo;
    const __nv_bfloat16* Wh = g_Whi + (mode ? WOFF : 0);
    const __nv_bfloat16* Wl = g_Wlo + (mode ? WOFF : 0);

    const int m0 = blockIdx.y*128, c0 = blockIdx.x*128;
    const int tid = threadIdx.x, lane = tid & 31, wid = tid >> 5;
    const int wm = wid & 3, wn = wid >> 2;
    const int grp = lane >> 2, tig = lane & 3;
    const int ra = tid >> 2, qa = tid & 3;

    const int laneA = ((lane&7) + ((lane>>3)&1)*8)*40 + (lane>>4)*8;
    const int laneB = ((lane&7) + (lane>>4)*8)*40 + ((lane>>3)&1)*8;

    const size_t oA0 = (size_t)(m0+ra)*DM    + qa*8;
    const size_t oA1 = (size_t)(m0+ra+64)*DM + qa*8;
    const size_t oB0 = (size_t)(c0+ra)*DM    + qa*8;
    const size_t oB1 = (size_t)(c0+ra+64)*DM + qa*8;
    const int s0 = ra*40 + qa*8, s1 = (ra+64)*40 + qa*8;

    float acc[2][8][4];
    #pragma unroll
    for (int mi=0;mi<2;mi++)
        #pragma unroll
        for (int ni=0;ni<8;ni++)
            #pragma unroll
            for (int c=0;c<4;c++) acc[mi][ni][c] = 0.f;

    {
        cp16(&As[0*GSTRIDE + s0], &Ah[oA0]);
        cp16(&As[0*GSTRIDE + s1], &Ah[oA1]);
        cp16(&As[1*GSTRIDE + s0], &Al[oA0]);
        cp16(&As[1*GSTRIDE + s1], &Al[oA1]);
        cp16(&Bs[0*GSTRIDE + s0], &Wh[oB0]);
        cp16(&Bs[0*GSTRIDE + s1], &Wh[oB1]);
        cp16(&Bs[1*GSTRIDE + s0], &Wl[oB0]);
        cp16(&Bs[1*GSTRIDE + s1], &Wl[oB1]);
        cp_commit();
    }

    #pragma unroll 1
    for (int t=0; t<24; ++t) {
        if (t < 23) {
            const int kn = (t+1)*32;
            const int sp = ((t+1)&1)*2;
            cp16(&As[(sp+0)*GSTRIDE + s0], &Ah[oA0 + kn]);
            cp16(&As[(sp+0)*GSTRIDE + s1], &Ah[oA1 + kn]);
            cp16(&As[(sp+1)*GSTRIDE + s0], &Al[oA0 + kn]);
            cp16(&As[(sp+1)*GSTRIDE + s1], &Al[oA1 + kn]);
            cp16(&Bs[(sp+0)*GSTRIDE + s0], &Wh[oB0 + kn]);
            cp16(&Bs[(sp+0)*GSTRIDE + s1], &Wh[oB1 + kn]);
            cp16(&Bs[(sp+1)*GSTRIDE + s0], &Wl[oB0 + kn]);
            cp16(&Bs[(sp+1)*GSTRIDE + s1], &Wl[oB1 + kn]);
            cp_commit();
            cp_wait<1>();
        } else {
            cp_wait<0>();
        }
        __syncthreads();

        const __nv_bfloat16* AsH = As + ((t&1)*2+0)*GSTRIDE;
        const __nv_bfloat16* AsL = As + ((t&1)*2+1)*GSTRIDE;
        const __nv_bfloat16* BsH = Bs + ((t&1)*2+0)*GSTRIDE;
        const __nv_bfloat16* BsL = Bs + ((t&1)*2+1)*GSTRIDE;

        #pragma unroll
        for (int ks=0; ks<2; ++ks) {
            const int kb0 = ks*16;
            uint32_t ah[2][4], al[2][4];
            #pragma unroll
            for (int mi=0;mi<2;mi++) {
                const int rb = (wm*32+mi*16)*40 + kb0 + laneA;
                ldsm_x4(ah[mi][0],ah[mi][1],ah[mi][2],ah[mi][3], scvta(&AsH[rb]));
                ldsm_x4(al[mi][0],al[mi][1],al[mi][2],al[mi][3], scvta(&AsL[rb]));
            }
            #pragma unroll
            for (int np=0;np<4;np++) {
                const int nb = (wn*64 + np*16)*40 + kb0 + laneB;
                uint32_t bh[4], bl[4];
                ldsm_x4(bh[0],bh[1],bh[2],bh[3], scvta(&BsH[nb]));
                ldsm_x4(bl[0],bl[1],bl[2],bl[3], scvta(&BsL[nb]));
                #pragma unroll
                for (int s=0;s<2;s++) {
                    const int ni = np*2+s;
                    #pragma unroll
                    for (int mi=0;mi<2;mi++) {
                        MMA_BF16(acc[mi][ni], ah[mi], bh[s*2], bh[s*2+1]);
                        MMA_BF16(acc[mi][ni], ah[mi], bl[s*2], bl[s*2+1]);
                        MMA_BF16(acc[mi][ni], al[mi], bh[s*2], bh[s*2+1]);
                    }
                }
            }
        }
        __syncthreads();
    }

    #pragma unroll
    for (int mi=0;mi<2;mi++) {
        #pragma unroll
        for (int ni=0;ni<8;ni++) {
            const int c = c0 + wn*64 + ni*8 + tig*2;
            const float b0v = bias[c], b1v = bias[c+1];
            #pragma unroll
            for (int hr=0;hr<2;hr++) {
                const int m = m0 + wm*32 + mi*16 + grp + hr*8;
                const float v0 = acc[mi][ni][hr*2+0] + b0v;
                const float v1 = acc[mi][ni][hr*2+1] + b1v;
                if (mode == 1) {
                    *(float2*)&out[(size_t)m*DM + c] = make_float2(v0, v1);
                } else {
                    const int t  = (c >= 1536) ? 2 : (c >= 768 ? 1 : 0);
                    const int rr = c - t*DM;
                    const int hh = rr >> 6, d = rr & 63;
                    const int b_ = m >> 10, n = m & 1023;
                    const size_t di = ((size_t)((b_*NH+hh)*NSEQ + n))*HD + d;
                    if (t == 0) {
                        *(float2*)&g_Q[di] = make_float2(v0, v1);
                        *(uint32_t*)&g_Qh16[di] = pack_h2(v0, v1);
                    } else if (t == 1) {
                        uint32_t hh32, ll32;
                        split2h(v0, v1, hh32, ll32);
                        *(uint32_t*)&g_Kh16[di] = hh32;
                        *(uint32_t*)&g_Kl16[di] = ll32;
                    } else {
                        *(float2*)&g_V[di] = make_float2(v0, v1);
                    }
                }
            }
        }
    }
}

// ---------------------------------------------------------------------------
// V transpose + fp16 split: g_VT*16[bh][d][k]
// ---------------------------------------------------------------------------
__global__ __launch_bounds__(256) void vtrans_kernel()
{
    __shared__ float ts[64*68];
    const int bh = blockIdx.y, k0 = blockIdx.x*64;
    const int tid = threadIdx.x;
    #pragma unroll
    for (int it=0; it<4; ++it) {
        int idx = it*256 + tid;
        int k = idx >> 4, dq = idx & 15;
        float4 v = *(const float4*)&g_V[((size_t)(bh*NSEQ + k0 + k))*HD + dq*4];
        *(float4*)&ts[k*68 + dq*4] = v;
    }
    __syncthreads();
    const int d = tid >> 2, kq = tid & 3;
    uint32_t hw[8], lw[8];
    #pragma unroll
    for (int i=0;i<8;++i) {
        float f0 = ts[(kq*16 + 2*i  )*68 + d];
        float f1 = ts[(kq*16 + 2*i+1)*68 + d];
        split2h(f0, f1, hw[i], lw[i]);
    }
    const size_t base = ((size_t)(bh*HD + d))*NSEQ + k0 + kq*16;
    *(uint4*)&g_VTh16[base]   = make_uint4(hw[0], hw[1], hw[2], hw[3]);
    *(uint4*)&g_VTh16[base+8] = make_uint4(hw[4], hw[5], hw[6], hw[7]);
    *(uint4*)&g_VTl16[base]   = make_uint4(lw[0], lw[1], lw[2], lw[3]);
    *(uint4*)&g_VTl16[base+8] = make_uint4(lw[4], lw[5], lw[6], lw[7]);
}

// ---------------------------------------------------------------------------
__global__ __launch_bounds__(256) void rel_kernel(
    const float* __restrict__ rph, const float* __restrict__ rpw)
{
    __shared__ float qs[4*64];
    const int blk = blockIdx.x;
    const int bh = blk >> 8, ng = blk & 255;
    const int tid = threadIdx.x, ln = tid >> 6, t = tid & 63;
    const int n = (ng << 2) + ln;
    qs[ln*64 + t] = g_Q[((size_t)(bh*NSEQ + n))*HD + t];
    __syncthreads();

    const int j = t & 31, half = t >> 5;
    const int qh = n >> 5, qw = n & 31;
    const float* tab = half ? rpw : rph;
    const int ref = half ? qw : qh;
    const float4* row = (const float4*)&tab[(ref - j + 31)*HD];
    const float4* q4  = (const float4*)&qs[ln*64];
    float a = 0.f;
    #pragma unroll
    for (int d4=0; d4<16; ++d4) {
        float4 rr = row[d4], qq = q4[d4];
        a += rr.x*qq.x + rr.y*qq.y + rr.z*qq.z + rr.w*qq.w;
    }
    float* dst = half ? g_relw : g_relh;
    dst[((size_t)(bh*NSEQ + n))*32 + j] = a;
}

// ---------------------------------------------------------------------------
__global__ void vsum_kernel()
{
    __shared__ float red[256];
    const int bh = blockIdx.x, tid = threadIdx.x;
    const int d = tid & 63, part = tid >> 6;
    float s = 0.f;
    for (int k = part*256; k < part*256 + 256; ++k)
        s += g_V[((size_t)(bh*NSEQ + k))*HD + d];
    red[tid] = s;
    __syncthreads();
    if (tid < 64)
        g_vsum[bh*HD + tid] = red[tid] + red[tid+64] + red[tid+128] + red[tid+192];
}

// ---------------------------------------------------------------------------
// Flash attention v3: fp16 operands, 2-MMA S (Qh*Kh + Qh*Kl),
// single-fp16 P with fp16 hi/lo V (2-MMA PV). k-tile 64, 2 CTAs/SM.
// ---------------------------------------------------------------------------
#define QKS 72
#define KPL2 (64*QKS)
#define VPL2 (64*QKS)
#define FL_SMEM_BYTES (128*QKS*2 + 4*KPL2*2 + 4*VPL2*2 + 2*64*4)

__global__ __launch_bounds__(256,2) void flash_mma(const float* __restrict__ policy)
{
    extern __shared__ char smraw[];
    __half* Qh   = (__half*)smraw;                     // 128*QKS
    __half* Kbuf = Qh + 128*QKS;                       // [(stage*2+hl)][KPL2]
    __half* Vbuf = Kbuf + 4*KPL2;                      // [(stage*2+hl)][VPL2]
    float* pol_s = (float*)(Vbuf + 4*VPL2);            // [2][64]

    const int bh = blockIdx.y, q0 = blockIdx.x << 7;
    const int b_ = bh / NH, hh = bh - b_*NH;
    const int tid = threadIdx.x, lane = tid & 31, w = tid >> 5;
    const int grp = lane >> 2, tig = lane & 3;
    const int r0 = w*16 + grp, r1 = r0 + 8;
    const int qg0 = q0 + r0, qg1 = q0 + r1;

    const int laneAq = ((lane&7) + ((lane>>3)&1)*8)*QKS + (lane>>4)*8;
    const int laneBk = ((lane&7) + (lane>>4)*8)*QKS + ((lane>>3)&1)*8;
    const int laneBv = laneBk;

    // ---- Q tile fp16 hi (once)
    #pragma unroll
    for (int it=0; it<4; ++it) {
        int idx = it*256 + tid, r = idx >> 3, q = idx & 7;
        *(uint4*)&Qh[r*QKS + q*8] =
            *(const uint4*)&g_Qh16[((size_t)(bh*NSEQ + q0 + r))*HD + q*8];
    }

    // ---- rel_w in registers: col pattern repeats mod 32 across tiles
    float rwr[16];
    #pragma unroll
    for (int j=0; j<4; ++j) {
        float2 a = *(const float2*)&g_relw[((size_t)(bh*NSEQ + qg0))*32 + j*8 + tig*2];
        float2 b = *(const float2*)&g_relw[((size_t)(bh*NSEQ + qg1))*32 + j*8 + tig*2];
        rwr[j*2]     = a.x;  rwr[j*2+1]   = a.y;
        rwr[8+j*2]   = b.x;  rwr[8+j*2+1] = b.y;
    }

    // ---- tile loader (64 keys) into stage sp
    auto load_tile = [&](int kt, int sp) {
        const int kb = kt*64;
        #pragma unroll
        for (int it=0; it<2; ++it) {
            int idx = it*256 + tid;
            int kr = idx >> 3, q = idx & 7;
            cp16(&Kbuf[(sp*2+0)*KPL2 + kr*QKS + q*8],
                 &g_Kh16[((size_t)(bh*NSEQ + kb + kr))*HD + q*8]);
            cp16(&Kbuf[(sp*2+1)*KPL2 + kr*QKS + q*8],
                 &g_Kl16[((size_t)(bh*NSEQ + kb + kr))*HD + q*8]);
            cp16(&Vbuf[(sp*2+0)*VPL2 + kr*QKS + q*8],
                 &g_VTh16[((size_t)(bh*HD + kr))*NSEQ + kb + q*8]);
            cp16(&Vbuf[(sp*2+1)*VPL2 + kr*QKS + q*8],
                 &g_VTl16[((size_t)(bh*HD + kr))*NSEQ + kb + q*8]);
        }
        if (tid < 16) cp16(&pol_s[sp*64 + tid*4], &policy[(b_<<10) + kb + tid*4]);
        cp_commit();
    };

    load_tile(0, 0);
    load_tile(1, 1);

    float m0 = -CUDART_INF_F, m1 = -CUDART_INF_F, l0v = 0.f, l1v = 0.f;
    float o[8][4];
    #pragma unroll
    for (int nd=0; nd<8; ++nd) { o[nd][0]=o[nd][1]=o[nd][2]=o[nd][3]=0.f; }

    #pragma unroll 1
    for (int t=0; t<16; ++t) {
        const int k0 = t << 6;
        if (t < 15) cp_wait<1>(); else cp_wait<0>();
        __syncthreads();

        const __half* Kh  = Kbuf + ((t&1)*2+0)*KPL2;
        const __half* Kl  = Kbuf + ((t&1)*2+1)*KPL2;
        const __half* Vth = Vbuf + ((t&1)*2+0)*VPL2;
        const __half* Vtl = Vbuf + ((t&1)*2+1)*VPL2;
        const float* pol = pol_s + (t&1)*64;

        float2 rh0 = *(const float2*)&g_relh[((size_t)(bh*NSEQ + qg0))*32 + (k0>>5)];
        float2 rh1 = *(const float2*)&g_relh[((size_t)(bh*NSEQ + qg1))*32 + (k0>>5)];

        // ---- S = Q.K^T  (fp16: Qh*Kh + Qh*Kl)
        float acc[8][4];
        #pragma unroll
        for (int jb=0; jb<8; ++jb) { acc[jb][0]=acc[jb][1]=acc[jb][2]=acc[jb][3]=0.f; }

        #pragma unroll
        for (int kb=0; kb<4; ++kb) {
            const int kk0 = kb*16;
            uint32_t qhf[4];
            ldsm_x4(qhf[0],qhf[1],qhf[2],qhf[3], scvta(&Qh[w*16*QKS + kk0 + laneAq]));
            #pragma unroll
            for (int jp=0; jp<4; ++jp) {
                uint32_t kh[4], kl[4];
                ldsm_x4(kh[0],kh[1],kh[2],kh[3], scvta(&Kh[jp*16*QKS + kk0 + laneBk]));
                ldsm_x4(kl[0],kl[1],kl[2],kl[3], scvta(&Kl[jp*16*QKS + kk0 + laneBk]));
                #pragma unroll
                for (int s=0;s<2;s++) {
                    const int jb = jp*2+s;
                    MMA_F16(acc[jb], qhf, kh[s*2], kh[s*2+1]);
                    MMA_F16(acc[jb], qhf, kl[s*2], kl[s*2+1]);
                }
            }
        }

        // ---- bias + row max over this 64-key tile (online softmax)
        float tmax0 = -CUDART_INF_F, tmax1 = -CUDART_INF_F;
        #pragma unroll
        for (int jb=0; jb<8; ++jb) {
            const int khs = (jb >> 2) & 1;
            const float rhv0 = khs ? rh0.y : rh0.x;
            const float rhv1 = khs ? rh1.y : rh1.x;
            const int rwi = (jb & 3) * 2;
            acc[jb][0] = acc[jb][0]*SCALE + rhv0 + rwr[rwi];
            acc[jb][1] = acc[jb][1]*SCALE + rhv0 + rwr[rwi+1];
            acc[jb][2] = acc[jb][2]*SCALE + rhv1 + rwr[8+rwi];
            acc[jb][3] = acc[jb][3]*SCALE + rhv1 + rwr[8+rwi+1];
            tmax0 = fmaxf(tmax0, fmaxf(acc[jb][0], acc[jb][1]));
            tmax1 = fmaxf(tmax1, fmaxf(acc[jb][2], acc[jb][3]));
        }
        tmax0 = fmaxf(tmax0, __shfl_xor_sync(0xffffffffu, tmax0, 1));
        tmax0 = fmaxf(tmax0, __shfl_xor_sync(0xffffffffu, tmax0, 2));
        tmax1 = fmaxf(tmax1, __shfl_xor_sync(0xffffffffu, tmax1, 1));
        tmax1 = fmaxf(tmax1, __shfl_xor_sync(0xffffffffu, tmax1, 2));

        const float mn0 = fmaxf(m0, tmax0);
        const float mn1 = fmaxf(m1, tmax1);
        const float f0 = __expf(m0 - mn0);
        const float f1 = __expf(m1 - mn1);
        m0 = mn0; m1 = mn1;
        #pragma unroll
        for (int nd=0; nd<8; ++nd) {
            o[nd][0]*=f0; o[nd][1]*=f0; o[nd][2]*=f1; o[nd][3]*=f1;
        }

        float rs0 = 0.f, rs1 = 0.f;
        #pragma unroll
        for (int g=0; g<4; ++g) {
            uint32_t pA[2], pB[2];
            #pragma unroll
            for (int jj=0; jj<2; ++jj) {
                const int jb = g*2 + jj;
                const int cb = (jb<<3) + (tig<<1);
                const int kg = k0 + cb;
                const float ap00 = (kg   == qg0) ? 1.f : pol[cb];
                const float ap01 = (kg+1 == qg0) ? 1.f : pol[cb+1];
                const float ap10 = (kg   == qg1) ? 1.f : pol[cb];
                const float ap11 = (kg+1 == qg1) ? 1.f : pol[cb+1];
                const float e00 = __expf(acc[jb][0] - mn0) * ap00;
                const float e01 = __expf(acc[jb][1] - mn0) * ap01;
                const float e10 = __expf(acc[jb][2] - mn1) * ap10;
                const float e11 = __expf(acc[jb][3] - mn1) * ap11;
                rs0 += e00 + e01;
                rs1 += e10 + e11;
                pA[jj] = pack_h2(e00, e01);
                pB[jj] = pack_h2(e10, e11);
            }
            uint32_t af[4] = { pA[0], pB[0], pA[1], pB[1] };
            #pragma unroll
            for (int np=0; np<4; ++np) {
                uint32_t vh[4], vl[4];
                ldsm_x4(vh[0],vh[1],vh[2],vh[3], scvta(&Vth[np*16*QKS + g*16 + laneBv]));
                ldsm_x4(vl[0],vl[1],vl[2],vl[3], scvta(&Vtl[np*16*QKS + g*16 + laneBv]));
                #pragma unroll
                for (int s=0;s<2;s++) {
                    const int nd = np*2+s;
                    MMA_F16(o[nd], af, vh[s*2], vh[s*2+1]);
                    MMA_F16(o[nd], af, vl[s*2], vl[s*2+1]);
                }
            }
        }
        rs0 += __shfl_xor_sync(0xffffffffu, rs0, 1);
        rs0 += __shfl_xor_sync(0xffffffffu, rs0, 2);
        rs1 += __shfl_xor_sync(0xffffffffu, rs1, 1);
        rs1 += __shfl_xor_sync(0xffffffffu, rs1, 2);
        l0v = l0v*f0 + rs0;
        l1v = l1v*f1 + rs1;

        __syncthreads();                 // stage t&1 fully consumed by ALL warps
        if (t < 14) load_tile(t+2, t&1); // now safe to overwrite it
    }

    const float inv0 = 1.f / (l0v + EPSV);
    const float inv1 = 1.f / (l1v + EPSV);
    #pragma unroll
    for (int nd=0; nd<8; ++nd) {
        const int d = nd*8 + tig*2;
        const float2 vs = *(const float2*)&g_vsum[bh*HD + d];
        const float a0 = (o[nd][0] + EPSN*vs.x) * inv0;
        const float a1 = (o[nd][1] + EPSN*vs.y) * inv0;
        const float a2 = (o[nd][2] + EPSN*vs.x) * inv1;
        const float a3 = (o[nd][3] + EPSN*vs.y) * inv1;
        uint32_t h0,l0,h1,l1;
        split2(a0, a1, h0, l0);
        split2(a2, a3, h1, l1);
        const size_t base0 = ((size_t)(b_*NSEQ + qg0))*DM + hh*HD + d;
        const size_t base1 = ((size_t)(b_*NSEQ + qg1))*DM + hh*HD + d;
        *(uint32_t*)&g_Thi[base0] = h0;
        *(uint32_t*)&g_Tlo[base0] = l0;
        *(uint32_t*)&g_Thi[base1] = h1;
        *(uint32_t*)&g_Tlo[base1] = l1;
    }
}

// ---------------------------------------------------------------------------
extern "C" void kernel_launch(void* const* d_in, const int* in_sizes, int n_in,
                              void* d_out, int out_size)
{
    const float* x      = (const float*)d_in[0];
    const float* policy = (const float*)d_in[1];
    const float* qkv_w  = (const float*)d_in[2];
    const float* qkv_b  = (const float*)d_in[3];
    const float* proj_w = (const float*)d_in[4];
    const float* proj_b = (const float*)d_in[5];
    const float* rph    = (const float*)d_in[6];
    const float* rpw    = (const float*)d_in[7];
    float* out = (float*)d_out;

    cudaFuncSetAttribute(flash_mma,
        cudaFuncAttributeMaxDynamicSharedMemorySize, FL_SMEM_BYTES);
    cudaFuncSetAttribute(gemm_mma,
        cudaFuncAttributeMaxDynamicSharedMemorySize, GEMM_SMEM_BYTES);

    const int n4x = NB*NSEQ*DM/4, n4q = 2304*DM/4, n4p = DM*DM/4;
    split_kernel<<<(n4x+255)/256,256>>>(x,      0, n4x);
    split_kernel<<<(n4q+255)/256,256>>>(qkv_w,  1, n4q);
    split_kernel<<<(n4p+255)/256,256>>>(proj_w, 2, n4p);

    gemm_mma<<<dim3(18,64),256,GEMM_SMEM_BYTES>>>(qkv_b, nullptr, 0);
    vtrans_kernel<<<dim3(16,NBH),256>>>();
    rel_kernel<<<NBH*256,256>>>(rph, rpw);
    vsum_kernel<<<NBH,256>>>();
    flash_mma<<<dim3(8,NBH),256,FL_SMEM_BYTES>>>(policy);
    gemm_mma<<<dim3(6,64),256,GEMM_SMEM_BYTES>>>(proj_b, out, 1);
}

// round 16
// speedup vs baseline: 1.5836x; 1.5836x over previous
#include <cuda_runtime.h>
#include <cuda_bf16.h>
#include <cuda_fp16.h>
#include <math_constants.h>
#include <cstddef>
#include <cstdint>

#define NB 8
#define NH 12
#define HD 64
#define DM 768
#define NSEQ 1024
#define NBH 96
#define SCALE 0.125f
#define EPSV 1e-6f
#define EPSN (1e-6f/1024.0f)
#define WOFF (2304*768)

__device__ float g_Q[NBH*NSEQ*HD];
__device__ float g_V[NBH*NSEQ*HD];
__device__ float g_relh[NBH*NSEQ*32];
__device__ float g_relw[NBH*NSEQ*32];
__device__ float g_vsum[NBH*HD];

__device__ __nv_bfloat16 g_Xhi[NB*NSEQ*DM], g_Xlo[NB*NSEQ*DM];
__device__ __nv_bfloat16 g_Whi[3072*DM],    g_Wlo[3072*DM];
__device__ __nv_bfloat16 g_Thi[NB*NSEQ*DM], g_Tlo[NB*NSEQ*DM];

// fp16 operands for flash (higher mantissa -> fewer MMA terms)
__device__ __half g_Qh16[NBH*NSEQ*HD];
__device__ __half g_Kh16[NBH*NSEQ*HD], g_Kl16[NBH*NSEQ*HD];
__device__ __half g_VTh16[NBH*HD*NSEQ], g_VTl16[NBH*HD*NSEQ];   // [bh][d][k]

#define MMA_BF16(d, a, b0, b1)                                             \
  asm volatile("mma.sync.aligned.m16n8k16.row.col.f32.bf16.bf16.f32 "      \
    "{%0,%1,%2,%3},{%4,%5,%6,%7},{%8,%9},{%0,%1,%2,%3};\n"                 \
    : "+f"(d[0]), "+f"(d[1]), "+f"(d[2]), "+f"(d[3])                       \
    : "r"(a[0]), "r"(a[1]), "r"(a[2]), "r"(a[3]), "r"(b0), "r"(b1))

#define MMA_F16(d, a, b0, b1)                                              \
  asm volatile("mma.sync.aligned.m16n8k16.row.col.f32.f16.f16.f32 "        \
    "{%0,%1,%2,%3},{%4,%5,%6,%7},{%8,%9},{%0,%1,%2,%3};\n"                 \
    : "+f"(d[0]), "+f"(d[1]), "+f"(d[2]), "+f"(d[3])                       \
    : "r"(a[0]), "r"(a[1]), "r"(a[2]), "r"(a[3]), "r"(b0), "r"(b1))

__device__ __forceinline__ uint32_t scvta(const void* p)
{
    return (uint32_t)__cvta_generic_to_shared(p);
}

__device__ __forceinline__ void ldsm_x4(uint32_t& r0, uint32_t& r1,
                                        uint32_t& r2, uint32_t& r3, uint32_t a)
{
    asm volatile("ldmatrix.sync.aligned.m8n8.x4.shared.b16 {%0,%1,%2,%3}, [%4];\n"
        : "=r"(r0), "=r"(r1), "=r"(r2), "=r"(r3) : "r"(a));
}

__device__ __forceinline__ void split2(float a, float b, uint32_t& hi, uint32_t& lo)
{
    __nv_bfloat162 h = __floats2bfloat162_rn(a, b);
    float ra = a - __bfloat162float(h.x);
    float rb = b - __bfloat162float(h.y);
    __nv_bfloat162 l = __floats2bfloat162_rn(ra, rb);
    hi = *(uint32_t*)&h;
    lo = *(uint32_t*)&l;
}

__device__ __forceinline__ void split2h(float a, float b, uint32_t& hi, uint32_t& lo)
{
    __half2 h = __floats2half2_rn(a, b);
    float ra = a - __low2float(h);
    float rb = b - __high2float(h);
    __half2 l = __floats2half2_rn(ra, rb);
    hi = *(uint32_t*)&h;
    lo = *(uint32_t*)&l;
}

__device__ __forceinline__ uint32_t pack_h2(float a, float b)
{
    __half2 h = __floats2half2_rn(a, b);
    return *(uint32_t*)&h;
}

__device__ __forceinline__ void cp16(void* smem, const void* gmem)
{
    uint32_t s = scvta(smem);
    asm volatile("cp.async.cg.shared.global [%0], [%1], 16;\n" :: "r"(s), "l"(gmem));
}
__device__ __forceinline__ void cp_commit()
{
    asm volatile("cp.async.commit_group;\n");
}
template<int N> __device__ __forceinline__ void cp_wait()
{
    asm volatile("cp.async.wait_group %0;\n" :: "n"(N));
}

// ---------------------------------------------------------------------------
__global__ void split_kernel(const float* __restrict__ src, int which, int n4)
{
    int i = blockIdx.x*256 + threadIdx.x;
    if (i >= n4) return;
    __nv_bfloat16 *hi, *lo;
    if (which == 0)      { hi = g_Xhi;        lo = g_Xlo; }
    else if (which == 1) { hi = g_Whi;        lo = g_Wlo; }
    else                 { hi = g_Whi + WOFF; lo = g_Wlo + WOFF; }
    float4 v = ((const float4*)src)[i];
    uint32_t h0, l0, h1, l1;
    split2(v.x, v.y, h0, l0);
    split2(v.z, v.w, h1, l1);
    ((uint32_t*)hi)[i*2]   = h0;
    ((uint32_t*)hi)[i*2+1] = h1;
    ((uint32_t*)lo)[i*2]   = l0;
    ((uint32_t*)lo)[i*2+1] = l1;
}

// ---------------------------------------------------------------------------
// Tensor-core GEMM (HMMA bf16 3-term), cp.async double-buffered, 2 CTAs/SM.
// mode 0 epilogue emits fp16 flash operands.
// ---------------------------------------------------------------------------
#define GSTRIDE 5120
#define GEMM_SMEM_BYTES (2 * 4 * GSTRIDE * 2)

__global__ __launch_bounds__(256,2) void gemm_mma(
    const float* __restrict__ bias, float* __restrict__ out, int mode)
{
    extern __shared__ __nv_bfloat16 smg[];
    __nv_bfloat16* As = smg;
    __nv_bfloat16* Bs = smg + 2*2*GSTRIDE;
    const __nv_bfloat16* Ah = mode ? g_Thi : g_Xhi;
    const __nv_bfloat16* Al = mode ? g_Tlo : g_Xlo;
    const __nv_bfloat16* Wh = g_Whi + (mode ? WOFF : 0);
    const __nv_bfloat16* Wl = g_Wlo + (mode ? WOFF : 0);

    const int m0 = blockIdx.y*128, c0 = blockIdx.x*128;
    const int tid = threadIdx.x, lane = tid & 31, wid = tid >> 5;
    const int wm = wid & 3, wn = wid >> 2;
    const int grp = lane >> 2, tig = lane & 3;
    const int ra = tid >> 2, qa = tid & 3;

    const int laneA = ((lane&7) + ((lane>>3)&1)*8)*40 + (lane>>4)*8;
    const int laneB = ((lane&7) + (lane>>4)*8)*40 + ((lane>>3)&1)*8;

    const size_t oA0 = (size_t)(m0+ra)*DM    + qa*8;
    const size_t oA1 = (size_t)(m0+ra+64)*DM + qa*8;
    const size_t oB0 = (size_t)(c0+ra)*DM    + qa*8;
    const size_t oB1 = (size_t)(c0+ra+64)*DM + qa*8;
    const int s0 = ra*40 + qa*8, s1 = (ra+64)*40 + qa*8;

    float acc[2][8][4];
    #pragma unroll
    for (int mi=0;mi<2;mi++)
        #pragma unroll
        for (int ni=0;ni<8;ni++)
            #pragma unroll
            for (int c=0;c<4;c++) acc[mi][ni][c] = 0.f;

    {
        cp16(&As[0*GSTRIDE + s0], &Ah[oA0]);
        cp16(&As[0*GSTRIDE + s1], &Ah[oA1]);
        cp16(&As[1*GSTRIDE + s0], &Al[oA0]);
        cp16(&As[1*GSTRIDE + s1], &Al[oA1]);
        cp16(&Bs[0*GSTRIDE + s0], &Wh[oB0]);
        cp16(&Bs[0*GSTRIDE + s1], &Wh[oB1]);
        cp16(&Bs[1*GSTRIDE + s0], &Wl[oB0]);
        cp16(&Bs[1*GSTRIDE + s1], &Wl[oB1]);
        cp_commit();
    }

    #pragma unroll 1
    for (int t=0; t<24; ++t) {
        if (t < 23) {
            const int kn = (t+1)*32;
            const int sp = ((t+1)&1)*2;
            cp16(&As[(sp+0)*GSTRIDE + s0], &Ah[oA0 + kn]);
            cp16(&As[(sp+0)*GSTRIDE + s1], &Ah[oA1 + kn]);
            cp16(&As[(sp+1)*GSTRIDE + s0], &Al[oA0 + kn]);
            cp16(&As[(sp+1)*GSTRIDE + s1], &Al[oA1 + kn]);
            cp16(&Bs[(sp+0)*GSTRIDE + s0], &Wh[oB0 + kn]);
            cp16(&Bs[(sp+0)*GSTRIDE + s1], &Wh[oB1 + kn]);
            cp16(&Bs[(sp+1)*GSTRIDE + s0], &Wl[oB0 + kn]);
            cp16(&Bs[(sp+1)*GSTRIDE + s1], &Wl[oB1 + kn]);
            cp_commit();
            cp_wait<1>();
        } else {
            cp_wait<0>();
        }
        __syncthreads();

        const __nv_bfloat16* AsH = As + ((t&1)*2+0)*GSTRIDE;
        const __nv_bfloat16* AsL = As + ((t&1)*2+1)*GSTRIDE;
        const __nv_bfloat16* BsH = Bs + ((t&1)*2+0)*GSTRIDE;
        const __nv_bfloat16* BsL = Bs + ((t&1)*2+1)*GSTRIDE;

        #pragma unroll
        for (int ks=0; ks<2; ++ks) {
            const int kb0 = ks*16;
            uint32_t ah[2][4], al[2][4];
            #pragma unroll
            for (int mi=0;mi<2;mi++) {
                const int rb = (wm*32+mi*16)*40 + kb0 + laneA;
                ldsm_x4(ah[mi][0],ah[mi][1],ah[mi][2],ah[mi][3], scvta(&AsH[rb]));
                ldsm_x4(al[mi][0],al[mi][1],al[mi][2],al[mi][3], scvta(&AsL[rb]));
            }
            #pragma unroll
            for (int np=0;np<4;np++) {
                const int nb = (wn*64 + np*16)*40 + kb0 + laneB;
                uint32_t bh[4], bl[4];
                ldsm_x4(bh[0],bh[1],bh[2],bh[3], scvta(&BsH[nb]));
                ldsm_x4(bl[0],bl[1],bl[2],bl[3], scvta(&BsL[nb]));
                #pragma unroll
                for (int s=0;s<2;s++) {
                    const int ni = np*2+s;
                    #pragma unroll
                    for (int mi=0;mi<2;mi++) {
                        MMA_BF16(acc[mi][ni], ah[mi], bh[s*2], bh[s*2+1]);
                        MMA_BF16(acc[mi][ni], ah[mi], bl[s*2], bl[s*2+1]);
                        MMA_BF16(acc[mi][ni], al[mi], bh[s*2], bh[s*2+1]);
                    }
                }
            }
        }
        __syncthreads();
    }

    #pragma unroll
    for (int mi=0;mi<2;mi++) {
        #pragma unroll
        for (int ni=0;ni<8;ni++) {
            const int c = c0 + wn*64 + ni*8 + tig*2;
            const float b0v = bias[c], b1v = bias[c+1];
            #pragma unroll
            for (int hr=0;hr<2;hr++) {
                const int m = m0 + wm*32 + mi*16 + grp + hr*8;
                const float v0 = acc[mi][ni][hr*2+0] + b0v;
                const float v1 = acc[mi][ni][hr*2+1] + b1v;
                if (mode == 1) {
                    *(float2*)&out[(size_t)m*DM + c] = make_float2(v0, v1);
                } else {
                    const int t  = (c >= 1536) ? 2 : (c >= 768 ? 1 : 0);
                    const int rr = c - t*DM;
                    const int hh = rr >> 6, d = rr & 63;
                    const int b_ = m >> 10, n = m & 1023;
                    const size_t di = ((size_t)((b_*NH+hh)*NSEQ + n))*HD + d;
                    if (t == 0) {
                        *(float2*)&g_Q[di] = make_float2(v0, v1);
                        *(uint32_t*)&g_Qh16[di] = pack_h2(v0, v1);
                    } else if (t == 1) {
                        uint32_t hh32, ll32;
                        split2h(v0, v1, hh32, ll32);
                        *(uint32_t*)&g_Kh16[di] = hh32;
                        *(uint32_t*)&g_Kl16[di] = ll32;
                    } else {
                        *(float2*)&g_V[di] = make_float2(v0, v1);
                    }
                }
            }
        }
    }
}

// ---------------------------------------------------------------------------
// V transpose + fp16 split: g_VT*16[bh][d][k]
// ---------------------------------------------------------------------------
__global__ __launch_bounds__(256) void vtrans_kernel()
{
    __shared__ float ts[64*68];
    const int bh = blockIdx.y, k0 = blockIdx.x*64;
    const int tid = threadIdx.x;
    #pragma unroll
    for (int it=0; it<4; ++it) {
        int idx = it*256 + tid;
        int k = idx >> 4, dq = idx & 15;
        float4 v = *(const float4*)&g_V[((size_t)(bh*NSEQ + k0 + k))*HD + dq*4];
        *(float4*)&ts[k*68 + dq*4] = v;
    }
    __syncthreads();
    const int d = tid >> 2, kq = tid & 3;
    uint32_t hw[8], lw[8];
    #pragma unroll
    for (int i=0;i<8;++i) {
        float f0 = ts[(kq*16 + 2*i  )*68 + d];
        float f1 = ts[(kq*16 + 2*i+1)*68 + d];
        split2h(f0, f1, hw[i], lw[i]);
    }
    const size_t base = ((size_t)(bh*HD + d))*NSEQ + k0 + kq*16;
    *(uint4*)&g_VTh16[base]   = make_uint4(hw[0], hw[1], hw[2], hw[3]);
    *(uint4*)&g_VTh16[base+8] = make_uint4(hw[4], hw[5], hw[6], hw[7]);
    *(uint4*)&g_VTl16[base]   = make_uint4(lw[0], lw[1], lw[2], lw[3]);
    *(uint4*)&g_VTl16[base+8] = make_uint4(lw[4], lw[5], lw[6], lw[7]);
}

// ---------------------------------------------------------------------------
__global__ __launch_bounds__(256) void rel_kernel(
    const float* __restrict__ rph, const float* __restrict__ rpw)
{
    __shared__ float qs[4*64];
    const int blk = blockIdx.x;
    const int bh = blk >> 8, ng = blk & 255;
    const int tid = threadIdx.x, ln = tid >> 6, t = tid & 63;
    const int n = (ng << 2) + ln;
    qs[ln*64 + t] = g_Q[((size_t)(bh*NSEQ + n))*HD + t];
    __syncthreads();

    const int j = t & 31, half = t >> 5;
    const int qh = n >> 5, qw = n & 31;
    const float* tab = half ? rpw : rph;
    const int ref = half ? qw : qh;
    const float4* row = (const float4*)&tab[(ref - j + 31)*HD];
    const float4* q4  = (const float4*)&qs[ln*64];
    float a = 0.f;
    #pragma unroll
    for (int d4=0; d4<16; ++d4) {
        float4 rr = row[d4], qq = q4[d4];
        a += rr.x*qq.x + rr.y*qq.y + rr.z*qq.z + rr.w*qq.w;
    }
    float* dst = half ? g_relw : g_relh;
    dst[((size_t)(bh*NSEQ + n))*32 + j] = a;
}

// ---------------------------------------------------------------------------
__global__ void vsum_kernel()
{
    __shared__ float red[256];
    const int bh = blockIdx.x, tid = threadIdx.x;
    const int d = tid & 63, part = tid >> 6;
    float s = 0.f;
    for (int k = part*256; k < part*256 + 256; ++k)
        s += g_V[((size_t)(bh*NSEQ + k))*HD + d];
    red[tid] = s;
    __syncthreads();
    if (tid < 64)
        g_vsum[bh*HD + tid] = red[tid] + red[tid+64] + red[tid+128] + red[tid+192];
}

// ---------------------------------------------------------------------------
// Flash attention v3: fp16 operands, 2-MMA S (Qh*Kh + Qh*Kl),
// single-fp16 P with fp16 hi/lo V (2-MMA PV). k-tile 64, 2 CTAs/SM.
// ---------------------------------------------------------------------------
#define QKS 72
#define KPL2 (64*QKS)
#define VPL2 (64*QKS)
#define FL_SMEM_BYTES (128*QKS*2 + 4*KPL2*2 + 4*VPL2*2 + 2*64*4)

__global__ __launch_bounds__(256,2) void flash_mma(const float* __restrict__ policy)
{
    extern __shared__ char smraw[];
    __half* Qh   = (__half*)smraw;                     // 128*QKS
    __half* Kbuf = Qh + 128*QKS;                       // [(stage*2+hl)][KPL2]
    __half* Vbuf = Kbuf + 4*KPL2;                      // [(stage*2+hl)][VPL2]
    float* pol_s = (float*)(Vbuf + 4*VPL2);            // [2][64]

    const int bh = blockIdx.y, q0 = blockIdx.x << 7;
    const int b_ = bh / NH, hh = bh - b_*NH;
    const int tid = threadIdx.x, lane = tid & 31, w = tid >> 5;
    const int grp = lane >> 2, tig = lane & 3;
    const int r0 = w*16 + grp, r1 = r0 + 8;
    const int qg0 = q0 + r0, qg1 = q0 + r1;

    const int laneAq = ((lane&7) + ((lane>>3)&1)*8)*QKS + (lane>>4)*8;
    const int laneBk = ((lane&7) + (lane>>4)*8)*QKS + ((lane>>3)&1)*8;
    const int laneBv = laneBk;

    // ---- Q tile fp16 hi (once)
    #pragma unroll
    for (int it=0; it<4; ++it) {
        int idx = it*256 + tid, r = idx >> 3, q = idx & 7;
        *(uint4*)&Qh[r*QKS + q*8] =
            *(const uint4*)&g_Qh16[((size_t)(bh*NSEQ + q0 + r))*HD + q*8];
    }

    // ---- rel_w in registers: col pattern repeats mod 32 across tiles
    float rwr[16];
    #pragma unroll
    for (int j=0; j<4; ++j) {
        float2 a = *(const float2*)&g_relw[((size_t)(bh*NSEQ + qg0))*32 + j*8 + tig*2];
        float2 b = *(const float2*)&g_relw[((size_t)(bh*NSEQ + qg1))*32 + j*8 + tig*2];
        rwr[j*2]     = a.x;  rwr[j*2+1]   = a.y;
        rwr[8+j*2]   = b.x;  rwr[8+j*2+1] = b.y;
    }

    // ---- tile loader (64 keys) into stage sp
    auto load_tile = [&](int kt, int sp) {
        const int kb = kt*64;
        #pragma unroll
        for (int it=0; it<2; ++it) {
            int idx = it*256 + tid;
            int kr = idx >> 3, q = idx & 7;
            cp16(&Kbuf[(sp*2+0)*KPL2 + kr*QKS + q*8],
                 &g_Kh16[((size_t)(bh*NSEQ + kb + kr))*HD + q*8]);
            cp16(&Kbuf[(sp*2+1)*KPL2 + kr*QKS + q*8],
                 &g_Kl16[((size_t)(bh*NSEQ + kb + kr))*HD + q*8]);
            cp16(&Vbuf[(sp*2+0)*VPL2 + kr*QKS + q*8],
                 &g_VTh16[((size_t)(bh*HD + kr))*NSEQ + kb + q*8]);
            cp16(&Vbuf[(sp*2+1)*VPL2 + kr*QKS + q*8],
                 &g_VTl16[((size_t)(bh*HD + kr))*NSEQ + kb + q*8]);
        }
        if (tid < 16) cp16(&pol_s[sp*64 + tid*4], &policy[(b_<<10) + kb + tid*4]);
        cp_commit();
    };

    load_tile(0, 0);
    load_tile(1, 1);

    float m0 = -CUDART_INF_F, m1 = -CUDART_INF_F, l0v = 0.f, l1v = 0.f;
    float o[8][4];
    #pragma unroll
    for (int nd=0; nd<8; ++nd) { o[nd][0]=o[nd][1]=o[nd][2]=o[nd][3]=0.f; }

    #pragma unroll 1
    for (int t=0; t<16; ++t) {
        const int k0 = t << 6;
        if (t < 15) cp_wait<1>(); else cp_wait<0>();
        __syncthreads();

        const __half* Kh  = Kbuf + ((t&1)*2+0)*KPL2;
        const __half* Kl  = Kbuf + ((t&1)*2+1)*KPL2;
        const __half* Vth = Vbuf + ((t&1)*2+0)*VPL2;
        const __half* Vtl = Vbuf + ((t&1)*2+1)*VPL2;
        const float* pol = pol_s + (t&1)*64;

        float2 rh0 = *(const float2*)&g_relh[((size_t)(bh*NSEQ + qg0))*32 + (k0>>5)];
        float2 rh1 = *(const float2*)&g_relh[((size_t)(bh*NSEQ + qg1))*32 + (k0>>5)];

        // ---- S = Q.K^T  (fp16: Qh*Kh + Qh*Kl)
        float acc[8][4];
        #pragma unroll
        for (int jb=0; jb<8; ++jb) { acc[jb][0]=acc[jb][1]=acc[jb][2]=acc[jb][3]=0.f; }

        #pragma unroll
        for (int kb=0; kb<4; ++kb) {
            const int kk0 = kb*16;
            uint32_t qhf[4];
            ldsm_x4(qhf[0],qhf[1],qhf[2],qhf[3], scvta(&Qh[w*16*QKS + kk0 + laneAq]));
            #pragma unroll
            for (int jp=0; jp<4; ++jp) {
                uint32_t kh[4], kl[4];
                ldsm_x4(kh[0],kh[1],kh[2],kh[3], scvta(&Kh[jp*16*QKS + kk0 + laneBk]));
                ldsm_x4(kl[0],kl[1],kl[2],kl[3], scvta(&Kl[jp*16*QKS + kk0 + laneBk]));
                #pragma unroll
                for (int s=0;s<2;s++) {
                    const int jb = jp*2+s;
                    MMA_F16(acc[jb], qhf, kh[s*2], kh[s*2+1]);
                    MMA_F16(acc[jb], qhf, kl[s*2], kl[s*2+1]);
                }
            }
        }

        // ---- bias + row max over this 64-key tile (online softmax)
        float tmax0 = -CUDART_INF_F, tmax1 = -CUDART_INF_F;
        #pragma unroll
        for (int jb=0; jb<8; ++jb) {
            const int khs = (jb >> 2) & 1;
            const float rhv0 = khs ? rh0.y : rh0.x;
            const float rhv1 = khs ? rh1.y : rh1.x;
            const int rwi = (jb & 3) * 2;
            acc[jb][0] = acc[jb][0]*SCALE + rhv0 + rwr[rwi];
            acc[jb][1] = acc[jb][1]*SCALE + rhv0 + rwr[rwi+1];
            acc[jb][2] = acc[jb][2]*SCALE + rhv1 + rwr[8+rwi];
            acc[jb][3] = acc[jb][3]*SCALE + rhv1 + rwr[8+rwi+1];
            tmax0 = fmaxf(tmax0, fmaxf(acc[jb][0], acc[jb][1]));
            tmax1 = fmaxf(tmax1, fmaxf(acc[jb][2], acc[jb][3]));
        }
        tmax0 = fmaxf(tmax0, __shfl_xor_sync(0xffffffffu, tmax0, 1));
        tmax0 = fmaxf(tmax0, __shfl_xor_sync(0xffffffffu, tmax0, 2));
        tmax1 = fmaxf(tmax1, __shfl_xor_sync(0xffffffffu, tmax1, 1));
        tmax1 = fmaxf(tmax1, __shfl_xor_sync(0xffffffffu, tmax1, 2));

        const float mn0 = fmaxf(m0, tmax0);
        const float mn1 = fmaxf(m1, tmax1);
        const float f0 = __expf(m0 - mn0);
        const float f1 = __expf(m1 - mn1);
        m0 = mn0; m1 = mn1;
        #pragma unroll
        for (int nd=0; nd<8; ++nd) {
            o[nd][0]*=f0; o[nd][1]*=f0; o[nd][2]*=f1; o[nd][3]*=f1;
        }

        float rs0 = 0.f, rs1 = 0.f;
        #pragma unroll
        for (int g=0; g<4; ++g) {
            uint32_t pA[2], pB[2];
            #pragma unroll
            for (int jj=0; jj<2; ++jj) {
                const int jb = g*2 + jj;
                const int cb = (jb<<3) + (tig<<1);
                const int kg = k0 + cb;
                const float ap00 = (kg   == qg0) ? 1.f : pol[cb];
                const float ap01 = (kg+1 == qg0) ? 1.f : pol[cb+1];
                const float ap10 = (kg   == qg1) ? 1.f : pol[cb];
                const float ap11 = (kg+1 == qg1) ? 1.f : pol[cb+1];
                const float e00 = __expf(acc[jb][0] - mn0) * ap00;
                const float e01 = __expf(acc[jb][1] - mn0) * ap01;
                const float e10 = __expf(acc[jb][2] - mn1) * ap10;
                const float e11 = __expf(acc[jb][3] - mn1) * ap11;
                rs0 += e00 + e01;
                rs1 += e10 + e11;
                pA[jj] = pack_h2(e00, e01);
                pB[jj] = pack_h2(e10, e11);
            }
            uint32_t af[4] = { pA[0], pB[0], pA[1], pB[1] };
            #pragma unroll
            for (int np=0; np<4; ++np) {
                uint32_t vh[4], vl[4];
                ldsm_x4(vh[0],vh[1],vh[2],vh[3], scvta(&Vth[np*16*QKS + g*16 + laneBv]));
                ldsm_x4(vl[0],vl[1],vl[2],vl[3], scvta(&Vtl[np*16*QKS + g*16 + laneBv]));
                #pragma unroll
                for (int s=0;s<2;s++) {
                    const int nd = np*2+s;
                    MMA_F16(o[nd], af, vh[s*2], vh[s*2+1]);
                    MMA_F16(o[nd], af, vl[s*2], vl[s*2+1]);
                }
            }
        }
        rs0 += __shfl_xor_sync(0xffffffffu, rs0, 1);
        rs0 += __shfl_xor_sync(0xffffffffu, rs0, 2);
        rs1 += __shfl_xor_sync(0xffffffffu, rs1, 1);
        rs1 += __shfl_xor_sync(0xffffffffu, rs1, 2);
        l0v = l0v*f0 + rs0;
        l1v = l1v*f1 + rs1;

        __syncthreads();                 // stage t&1 fully consumed by ALL warps
        if (t < 14) load_tile(t+2, t&1); // now safe to overwrite it
    }

    const float inv0 = 1.f / (l0v + EPSV);
    const float inv1 = 1.f / (l1v + EPSV);
    #pragma unroll
    for (int nd=0; nd<8; ++nd) {
        const int d = nd*8 + tig*2;
        const float2 vs = *(const float2*)&g_vsum[bh*HD + d];
        const float a0 = (o[nd][0] + EPSN*vs.x) * inv0;
        const float a1 = (o[nd][1] + EPSN*vs.y) * inv0;
        const float a2 = (o[nd][2] + EPSN*vs.x) * inv1;
        const float a3 = (o[nd][3] + EPSN*vs.y) * inv1;
        uint32_t h0,l0,h1,l1;
        split2(a0, a1, h0, l0);
        split2(a2, a3, h1, l1);
        const size_t base0 = ((size_t)(b_*NSEQ + qg0))*DM + hh*HD + d;
        const size_t base1 = ((size_t)(b_*NSEQ + qg1))*DM + hh*HD + d;
        *(uint32_t*)&g_Thi[base0] = h0;
        *(uint32_t*)&g_Tlo[base0] = l0;
        *(uint32_t*)&g_Thi[base1] = h1;
        *(uint32_t*)&g_Tlo[base1] = l1;
    }
}

// ---------------------------------------------------------------------------
extern "C" void kernel_launch(void* const* d_in, const int* in_sizes, int n_in,
                              void* d_out, int out_size)
{
    const float* x      = (const float*)d_in[0];
    const float* policy = (const float*)d_in[1];
    const float* qkv_w  = (const float*)d_in[2];
    const float* qkv_b  = (const float*)d_in[3];
    const float* proj_w = (const float*)d_in[4];
    const float* proj_b = (const float*)d_in[5];
    const float* rph    = (const float*)d_in[6];
    const float* rpw    = (const float*)d_in[7];
    float* out = (float*)d_out;

    cudaFuncSetAttribute(flash_mma,
        cudaFuncAttributeMaxDynamicSharedMemorySize, FL_SMEM_BYTES);
    cudaFuncSetAttribute(gemm_mma,
        cudaFuncAttributeMaxDynamicSharedMemorySize, GEMM_SMEM_BYTES);

    const int n4x = NB*NSEQ*DM/4, n4q = 2304*DM/4, n4p = DM*DM/4;
    split_kernel<<<(n4x+255)/256,256>>>(x,      0, n4x);
    split_kernel<<<(n4q+255)/256,256>>>(qkv_w,  1, n4q);
    split_kernel<<<(n4p+255)/256,256>>>(proj_w, 2, n4p);

    gemm_mma<<<dim3(18,64),256,GEMM_SMEM_BYTES>>>(qkv_b, nullptr, 0);
    vtrans_kernel<<<dim3(16,NBH),256>>>();
    rel_kernel<<<NBH*256,256>>>(rph, rpw);
    vsum_kernel<<<NBH,256>>>();
    flash_mma<<<dim3(8,NBH),256,FL_SMEM_BYTES>>>(policy);
    gemm_mma<<<dim3(6,64),256,GEMM_SMEM_BYTES>>>(proj_b, out, 1);
}

// round 17
// speedup vs baseline: 1.7816x; 1.1250x over previous
#include <cuda_runtime.h>
#include <cuda_bf16.h>
#include <cuda_fp16.h>
#include <math_constants.h>
#include <cstddef>
#include <cstdint>

#define NB 8
#define NH 12
#define HD 64
#define DM 768
#define NSEQ 1024
#define NBH 96
#define SCALE 0.125f
#define EPSV 1e-6f
#define EPSN (1e-6f/1024.0f)
#define WOFF (2304*768)

__device__ float g_Q[NBH*NSEQ*HD];
__device__ float g_V[NBH*NSEQ*HD];
__device__ float g_relh[NBH*NSEQ*32];
__device__ float g_relw[NBH*NSEQ*32];
__device__ float g_vsum[NBH*HD];

// fp16 operands, 2-term split scheme (A: hi only; B/weights: hi+lo)
__device__ __half g_Xh16[NB*NSEQ*DM];
__device__ __half g_Wh16[3072*DM], g_Wl16[3072*DM];   // qkv_w ++ proj_w
__device__ __half g_Th16[NB*NSEQ*DM];                 // attention output (hi only)
__device__ __half g_Qh16[NBH*NSEQ*HD];
__device__ __half g_Kh16[NBH*NSEQ*HD], g_Kl16[NBH*NSEQ*HD];
__device__ __half g_VTh16[NBH*HD*NSEQ], g_VTl16[NBH*HD*NSEQ];   // [bh][d][k]

#define MMA_F16(d, a, b0, b1)                                              \
  asm volatile("mma.sync.aligned.m16n8k16.row.col.f32.f16.f16.f32 "        \
    "{%0,%1,%2,%3},{%4,%5,%6,%7},{%8,%9},{%0,%1,%2,%3};\n"                 \
    : "+f"(d[0]), "+f"(d[1]), "+f"(d[2]), "+f"(d[3])                       \
    : "r"(a[0]), "r"(a[1]), "r"(a[2]), "r"(a[3]), "r"(b0), "r"(b1))

__device__ __forceinline__ uint32_t scvta(const void* p)
{
    return (uint32_t)__cvta_generic_to_shared(p);
}

__device__ __forceinline__ void ldsm_x4(uint32_t& r0, uint32_t& r1,
                                        uint32_t& r2, uint32_t& r3, uint32_t a)
{
    asm volatile("ldmatrix.sync.aligned.m8n8.x4.shared.b16 {%0,%1,%2,%3}, [%4];\n"
        : "=r"(r0), "=r"(r1), "=r"(r2), "=r"(r3) : "r"(a));
}

__device__ __forceinline__ void split2h(float a, float b, uint32_t& hi, uint32_t& lo)
{
    __half2 h = __floats2half2_rn(a, b);
    float ra = a - __low2float(h);
    float rb = b - __high2float(h);
    __half2 l = __floats2half2_rn(ra, rb);
    hi = *(uint32_t*)&h;
    lo = *(uint32_t*)&l;
}

__device__ __forceinline__ uint32_t pack_h2(float a, float b)
{
    __half2 h = __floats2half2_rn(a, b);
    return *(uint32_t*)&h;
}

__device__ __forceinline__ void cp16(void* smem, const void* gmem)
{
    uint32_t s = scvta(smem);
    asm volatile("cp.async.cg.shared.global [%0], [%1], 16;\n" :: "r"(s), "l"(gmem));
}
__device__ __forceinline__ void cp_commit()
{
    asm volatile("cp.async.commit_group;\n");
}
template<int N> __device__ __forceinline__ void cp_wait()
{
    asm volatile("cp.async.wait_group %0;\n" :: "n"(N));
}

// ---------------------------------------------------------------------------
// split fp32 -> fp16.  which 0: x -> hi only.  1: qkv_w hi+lo.  2: proj_w.
// ---------------------------------------------------------------------------
__global__ void split_kernel(const float* __restrict__ src, int which, int n4)
{
    int i = blockIdx.x*256 + threadIdx.x;
    if (i >= n4) return;
    float4 v = ((const float4*)src)[i];
    if (which == 0) {
        ((uint32_t*)g_Xh16)[i*2]   = pack_h2(v.x, v.y);
        ((uint32_t*)g_Xh16)[i*2+1] = pack_h2(v.z, v.w);
        return;
    }
    __half* hi = g_Wh16 + (which == 2 ? WOFF : 0);
    __half* lo = g_Wl16 + (which == 2 ? WOFF : 0);
    uint32_t h0, l0, h1, l1;
    split2h(v.x, v.y, h0, l0);
    split2h(v.z, v.w, h1, l1);
    ((uint32_t*)hi)[i*2]   = h0;
    ((uint32_t*)hi)[i*2+1] = h1;
    ((uint32_t*)lo)[i*2]   = l0;
    ((uint32_t*)lo)[i*2+1] = l1;
}

// ---------------------------------------------------------------------------
// Tensor-core GEMM, fp16 2-term (Ah*Bh + Ah*Bl), cp.async double-buffered.
// A: 1 plane/stage.  B: 2 planes/stage.  2 CTAs/SM.
// ---------------------------------------------------------------------------
#define GSTRIDE 5120
#define GEMM_SMEM_BYTES ((2*1 + 2*2) * GSTRIDE * 2)   // 61440

__global__ __launch_bounds__(256,2) void gemm_mma(
    const float* __restrict__ bias, float* __restrict__ out, int mode)
{
    extern __shared__ __half smg[];
    __half* As = smg;                     // [stage][128*40]
    __half* Bs = smg + 2*GSTRIDE;         // [(stage*2+hl)][128*40]
    const __half* Ah = mode ? g_Th16 : g_Xh16;
    const __half* Wh = g_Wh16 + (mode ? WOFF : 0);
    const __half* Wl = g_Wl16 + (mode ? WOFF : 0);

    const int m0 = blockIdx.y*128, c0 = blockIdx.x*128;
    const int tid = threadIdx.x, lane = tid & 31, wid = tid >> 5;
    const int wm = wid & 3, wn = wid >> 2;
    const int grp = lane >> 2, tig = lane & 3;
    const int ra = tid >> 2, qa = tid & 3;

    const int laneA = ((lane&7) + ((lane>>3)&1)*8)*40 + (lane>>4)*8;
    const int laneB = ((lane&7) + (lane>>4)*8)*40 + ((lane>>3)&1)*8;

    const size_t oA0 = (size_t)(m0+ra)*DM    + qa*8;
    const size_t oA1 = (size_t)(m0+ra+64)*DM + qa*8;
    const size_t oB0 = (size_t)(c0+ra)*DM    + qa*8;
    const size_t oB1 = (size_t)(c0+ra+64)*DM + qa*8;
    const int s0 = ra*40 + qa*8, s1 = (ra+64)*40 + qa*8;

    float acc[2][8][4];
    #pragma unroll
    for (int mi=0;mi<2;mi++)
        #pragma unroll
        for (int ni=0;ni<8;ni++)
            #pragma unroll
            for (int c=0;c<4;c++) acc[mi][ni][c] = 0.f;

    {
        cp16(&As[0*GSTRIDE + s0], &Ah[oA0]);
        cp16(&As[0*GSTRIDE + s1], &Ah[oA1]);
        cp16(&Bs[0*GSTRIDE + s0], &Wh[oB0]);
        cp16(&Bs[0*GSTRIDE + s1], &Wh[oB1]);
        cp16(&Bs[1*GSTRIDE + s0], &Wl[oB0]);
        cp16(&Bs[1*GSTRIDE + s1], &Wl[oB1]);
        cp_commit();
    }

    #pragma unroll 1
    for (int t=0; t<24; ++t) {
        if (t < 23) {
            const int kn = (t+1)*32;
            const int st = (t+1)&1;
            cp16(&As[st*GSTRIDE + s0], &Ah[oA0 + kn]);
            cp16(&As[st*GSTRIDE + s1], &Ah[oA1 + kn]);
            cp16(&Bs[(st*2+0)*GSTRIDE + s0], &Wh[oB0 + kn]);
            cp16(&Bs[(st*2+0)*GSTRIDE + s1], &Wh[oB1 + kn]);
            cp16(&Bs[(st*2+1)*GSTRIDE + s0], &Wl[oB0 + kn]);
            cp16(&Bs[(st*2+1)*GSTRIDE + s1], &Wl[oB1 + kn]);
            cp_commit();
            cp_wait<1>();
        } else {
            cp_wait<0>();
        }
        __syncthreads();

        const __half* AsC = As + (t&1)*GSTRIDE;
        const __half* BsH = Bs + ((t&1)*2+0)*GSTRIDE;
        const __half* BsL = Bs + ((t&1)*2+1)*GSTRIDE;

        #pragma unroll
        for (int ks=0; ks<2; ++ks) {
            const int kb0 = ks*16;
            uint32_t a_[2][4];
            #pragma unroll
            for (int mi=0;mi<2;mi++) {
                const int rb = (wm*32+mi*16)*40 + kb0 + laneA;
                ldsm_x4(a_[mi][0],a_[mi][1],a_[mi][2],a_[mi][3], scvta(&AsC[rb]));
            }
            #pragma unroll
            for (int np=0;np<4;np++) {
                const int nb = (wn*64 + np*16)*40 + kb0 + laneB;
                uint32_t bh[4], bl[4];
                ldsm_x4(bh[0],bh[1],bh[2],bh[3], scvta(&BsH[nb]));
                ldsm_x4(bl[0],bl[1],bl[2],bl[3], scvta(&BsL[nb]));
                #pragma unroll
                for (int s=0;s<2;s++) {
                    const int ni = np*2+s;
                    #pragma unroll
                    for (int mi=0;mi<2;mi++) {
                        MMA_F16(acc[mi][ni], a_[mi], bh[s*2], bh[s*2+1]);
                        MMA_F16(acc[mi][ni], a_[mi], bl[s*2], bl[s*2+1]);
                    }
                }
            }
        }
        __syncthreads();
    }

    #pragma unroll
    for (int mi=0;mi<2;mi++) {
        #pragma unroll
        for (int ni=0;ni<8;ni++) {
            const int c = c0 + wn*64 + ni*8 + tig*2;
            const float b0v = bias[c], b1v = bias[c+1];
            #pragma unroll
            for (int hr=0;hr<2;hr++) {
                const int m = m0 + wm*32 + mi*16 + grp + hr*8;
                const float v0 = acc[mi][ni][hr*2+0] + b0v;
                const float v1 = acc[mi][ni][hr*2+1] + b1v;
                if (mode == 1) {
                    *(float2*)&out[(size_t)m*DM + c] = make_float2(v0, v1);
                } else {
                    const int t  = (c >= 1536) ? 2 : (c >= 768 ? 1 : 0);
                    const int rr = c - t*DM;
                    const int hh = rr >> 6, d = rr & 63;
                    const int b_ = m >> 10, n = m & 1023;
                    const size_t di = ((size_t)((b_*NH+hh)*NSEQ + n))*HD + d;
                    if (t == 0) {
                        *(float2*)&g_Q[di] = make_float2(v0, v1);
                        *(uint32_t*)&g_Qh16[di] = pack_h2(v0, v1);
                    } else if (t == 1) {
                        uint32_t hh32, ll32;
                        split2h(v0, v1, hh32, ll32);
                        *(uint32_t*)&g_Kh16[di] = hh32;
                        *(uint32_t*)&g_Kl16[di] = ll32;
                    } else {
                        *(float2*)&g_V[di] = make_float2(v0, v1);
                    }
                }
            }
        }
    }
}

// ---------------------------------------------------------------------------
// V transpose + fp16 split: g_VT*16[bh][d][k]
// ---------------------------------------------------------------------------
__global__ __launch_bounds__(256) void vtrans_kernel()
{
    __shared__ float ts[64*68];
    const int bh = blockIdx.y, k0 = blockIdx.x*64;
    const int tid = threadIdx.x;
    #pragma unroll
    for (int it=0; it<4; ++it) {
        int idx = it*256 + tid;
        int k = idx >> 4, dq = idx & 15;
        float4 v = *(const float4*)&g_V[((size_t)(bh*NSEQ + k0 + k))*HD + dq*4];
        *(float4*)&ts[k*68 + dq*4] = v;
    }
    __syncthreads();
    const int d = tid >> 2, kq = tid & 3;
    uint32_t hw[8], lw[8];
    #pragma unroll
    for (int i=0;i<8;++i) {
        float f0 = ts[(kq*16 + 2*i  )*68 + d];
        float f1 = ts[(kq*16 + 2*i+1)*68 + d];
        split2h(f0, f1, hw[i], lw[i]);
    }
    const size_t base = ((size_t)(bh*HD + d))*NSEQ + k0 + kq*16;
    *(uint4*)&g_VTh16[base]   = make_uint4(hw[0], hw[1], hw[2], hw[3]);
    *(uint4*)&g_VTh16[base+8] = make_uint4(hw[4], hw[5], hw[6], hw[7]);
    *(uint4*)&g_VTl16[base]   = make_uint4(lw[0], lw[1], lw[2], lw[3]);
    *(uint4*)&g_VTl16[base+8] = make_uint4(lw[4], lw[5], lw[6], lw[7]);
}

// ---------------------------------------------------------------------------
__global__ __launch_bounds__(256) void rel_kernel(
    const float* __restrict__ rph, const float* __restrict__ rpw)
{
    __shared__ float qs[4*64];
    const int blk = blockIdx.x;
    const int bh = blk >> 8, ng = blk & 255;
    const int tid = threadIdx.x, ln = tid >> 6, t = tid & 63;
    const int n = (ng << 2) + ln;
    qs[ln*64 + t] = g_Q[((size_t)(bh*NSEQ + n))*HD + t];
    __syncthreads();

    const int j = t & 31, half = t >> 5;
    const int qh = n >> 5, qw = n & 31;
    const float* tab = half ? rpw : rph;
    const int ref = half ? qw : qh;
    const float4* row = (const float4*)&tab[(ref - j + 31)*HD];
    const float4* q4  = (const float4*)&qs[ln*64];
    float a = 0.f;
    #pragma unroll
    for (int d4=0; d4<16; ++d4) {
        float4 rr = row[d4], qq = q4[d4];
        a += rr.x*qq.x + rr.y*qq.y + rr.z*qq.z + rr.w*qq.w;
    }
    float* dst = half ? g_relw : g_relh;
    dst[((size_t)(bh*NSEQ + n))*32 + j] = a;
}

// ---------------------------------------------------------------------------
__global__ void vsum_kernel()
{
    __shared__ float red[256];
    const int bh = blockIdx.x, tid = threadIdx.x;
    const int d = tid & 63, part = tid >> 6;
    float s = 0.f;
    for (int k = part*256; k < part*256 + 256; ++k)
        s += g_V[((size_t)(bh*NSEQ + k))*HD + d];
    red[tid] = s;
    __syncthreads();
    if (tid < 64)
        g_vsum[bh*HD + tid] = red[tid] + red[tid+64] + red[tid+128] + red[tid+192];
}

// ---------------------------------------------------------------------------
// Flash attention v3 (proven R14): fp16 operands, 2-MMA S, 2-MMA PV.
// k-tile 64, 2 CTAs/SM.  Epilogue now emits fp16 hi only.
// ---------------------------------------------------------------------------
#define QKS 72
#define KPL2 (64*QKS)
#define VPL2 (64*QKS)
#define FL_SMEM_BYTES (128*QKS*2 + 4*KPL2*2 + 4*VPL2*2 + 2*64*4)

__global__ __launch_bounds__(256,2) void flash_mma(const float* __restrict__ policy)
{
    extern __shared__ char smraw[];
    __half* Qh   = (__half*)smraw;                     // 128*QKS
    __half* Kbuf = Qh + 128*QKS;                       // [(stage*2+hl)][KPL2]
    __half* Vbuf = Kbuf + 4*KPL2;                      // [(stage*2+hl)][VPL2]
    float* pol_s = (float*)(Vbuf + 4*VPL2);            // [2][64]

    const int bh = blockIdx.y, q0 = blockIdx.x << 7;
    const int b_ = bh / NH, hh = bh - b_*NH;
    const int tid = threadIdx.x, lane = tid & 31, w = tid >> 5;
    const int grp = lane >> 2, tig = lane & 3;
    const int r0 = w*16 + grp, r1 = r0 + 8;
    const int qg0 = q0 + r0, qg1 = q0 + r1;

    const int laneAq = ((lane&7) + ((lane>>3)&1)*8)*QKS + (lane>>4)*8;
    const int laneBk = ((lane&7) + (lane>>4)*8)*QKS + ((lane>>3)&1)*8;
    const int laneBv = laneBk;

    #pragma unroll
    for (int it=0; it<4; ++it) {
        int idx = it*256 + tid, r = idx >> 3, q = idx & 7;
        *(uint4*)&Qh[r*QKS + q*8] =
            *(const uint4*)&g_Qh16[((size_t)(bh*NSEQ + q0 + r))*HD + q*8];
    }

    float rwr[16];
    #pragma unroll
    for (int j=0; j<4; ++j) {
        float2 a = *(const float2*)&g_relw[((size_t)(bh*NSEQ + qg0))*32 + j*8 + tig*2];
        float2 b = *(const float2*)&g_relw[((size_t)(bh*NSEQ + qg1))*32 + j*8 + tig*2];
        rwr[j*2]     = a.x;  rwr[j*2+1]   = a.y;
        rwr[8+j*2]   = b.x;  rwr[8+j*2+1] = b.y;
    }

    auto load_tile = [&](int kt, int sp) {
        const int kb = kt*64;
        #pragma unroll
        for (int it=0; it<2; ++it) {
            int idx = it*256 + tid;
            int kr = idx >> 3, q = idx & 7;
            cp16(&Kbuf[(sp*2+0)*KPL2 + kr*QKS + q*8],
                 &g_Kh16[((size_t)(bh*NSEQ + kb + kr))*HD + q*8]);
            cp16(&Kbuf[(sp*2+1)*KPL2 + kr*QKS + q*8],
                 &g_Kl16[((size_t)(bh*NSEQ + kb + kr))*HD + q*8]);
            cp16(&Vbuf[(sp*2+0)*VPL2 + kr*QKS + q*8],
                 &g_VTh16[((size_t)(bh*HD + kr))*NSEQ + kb + q*8]);
            cp16(&Vbuf[(sp*2+1)*VPL2 + kr*QKS + q*8],
                 &g_VTl16[((size_t)(bh*HD + kr))*NSEQ + kb + q*8]);
        }
        if (tid < 16) cp16(&pol_s[sp*64 + tid*4], &policy[(b_<<10) + kb + tid*4]);
        cp_commit();
    };

    load_tile(0, 0);
    load_tile(1, 1);

    float m0 = -CUDART_INF_F, m1 = -CUDART_INF_F, l0v = 0.f, l1v = 0.f;
    float o[8][4];
    #pragma unroll
    for (int nd=0; nd<8; ++nd) { o[nd][0]=o[nd][1]=o[nd][2]=o[nd][3]=0.f; }

    #pragma unroll 1
    for (int t=0; t<16; ++t) {
        const int k0 = t << 6;
        if (t < 15) cp_wait<1>(); else cp_wait<0>();
        __syncthreads();

        const __half* Kh  = Kbuf + ((t&1)*2+0)*KPL2;
        const __half* Kl  = Kbuf + ((t&1)*2+1)*KPL2;
        const __half* Vth = Vbuf + ((t&1)*2+0)*VPL2;
        const __half* Vtl = Vbuf + ((t&1)*2+1)*VPL2;
        const float* pol = pol_s + (t&1)*64;

        float2 rh0 = *(const float2*)&g_relh[((size_t)(bh*NSEQ + qg0))*32 + (k0>>5)];
        float2 rh1 = *(const float2*)&g_relh[((size_t)(bh*NSEQ + qg1))*32 + (k0>>5)];

        float acc[8][4];
        #pragma unroll
        for (int jb=0; jb<8; ++jb) { acc[jb][0]=acc[jb][1]=acc[jb][2]=acc[jb][3]=0.f; }

        #pragma unroll
        for (int kb=0; kb<4; ++kb) {
            const int kk0 = kb*16;
            uint32_t qhf[4];
            ldsm_x4(qhf[0],qhf[1],qhf[2],qhf[3], scvta(&Qh[w*16*QKS + kk0 + laneAq]));
            #pragma unroll
            for (int jp=0; jp<4; ++jp) {
                uint32_t kh[4], kl[4];
                ldsm_x4(kh[0],kh[1],kh[2],kh[3], scvta(&Kh[jp*16*QKS + kk0 + laneBk]));
                ldsm_x4(kl[0],kl[1],kl[2],kl[3], scvta(&Kl[jp*16*QKS + kk0 + laneBk]));
                #pragma unroll
                for (int s=0;s<2;s++) {
                    const int jb = jp*2+s;
                    MMA_F16(acc[jb], qhf, kh[s*2], kh[s*2+1]);
                    MMA_F16(acc[jb], qhf, kl[s*2], kl[s*2+1]);
                }
            }
        }

        float tmax0 = -CUDART_INF_F, tmax1 = -CUDART_INF_F;
        #pragma unroll
        for (int jb=0; jb<8; ++jb) {
            const int khs = (jb >> 2) & 1;
            const float rhv0 = khs ? rh0.y : rh0.x;
            const float rhv1 = khs ? rh1.y : rh1.x;
            const int rwi = (jb & 3) * 2;
            acc[jb][0] = acc[jb][0]*SCALE + rhv0 + rwr[rwi];
            acc[jb][1] = acc[jb][1]*SCALE + rhv0 + rwr[rwi+1];
            acc[jb][2] = acc[jb][2]*SCALE + rhv1 + rwr[8+rwi];
            acc[jb][3] = acc[jb][3]*SCALE + rhv1 + rwr[8+rwi+1];
            tmax0 = fmaxf(tmax0, fmaxf(acc[jb][0], acc[jb][1]));
            tmax1 = fmaxf(tmax1, fmaxf(acc[jb][2], acc[jb][3]));
        }
        tmax0 = fmaxf(tmax0, __shfl_xor_sync(0xffffffffu, tmax0, 1));
        tmax0 = fmaxf(tmax0, __shfl_xor_sync(0xffffffffu, tmax0, 2));
        tmax1 = fmaxf(tmax1, __shfl_xor_sync(0xffffffffu, tmax1, 1));
        tmax1 = fmaxf(tmax1, __shfl_xor_sync(0xffffffffu, tmax1, 2));

        const float mn0 = fmaxf(m0, tmax0);
        const float mn1 = fmaxf(m1, tmax1);
        const float f0 = __expf(m0 - mn0);
        const float f1 = __expf(m1 - mn1);
        m0 = mn0; m1 = mn1;
        #pragma unroll
        for (int nd=0; nd<8; ++nd) {
            o[nd][0]*=f0; o[nd][1]*=f0; o[nd][2]*=f1; o[nd][3]*=f1;
        }

        float rs0 = 0.f, rs1 = 0.f;
        #pragma unroll
        for (int g=0; g<4; ++g) {
            uint32_t pA[2], pB[2];
            #pragma unroll
            for (int jj=0; jj<2; ++jj) {
                const int jb = g*2 + jj;
                const int cb = (jb<<3) + (tig<<1);
                const int kg = k0 + cb;
                const float ap00 = (kg   == qg0) ? 1.f : pol[cb];
                const float ap01 = (kg+1 == qg0) ? 1.f : pol[cb+1];
                const float ap10 = (kg   == qg1) ? 1.f : pol[cb];
                const float ap11 = (kg+1 == qg1) ? 1.f : pol[cb+1];
                const float e00 = __expf(acc[jb][0] - mn0) * ap00;
                const float e01 = __expf(acc[jb][1] - mn0) * ap01;
                const float e10 = __expf(acc[jb][2] - mn1) * ap10;
                const float e11 = __expf(acc[jb][3] - mn1) * ap11;
                rs0 += e00 + e01;
                rs1 += e10 + e11;
                pA[jj] = pack_h2(e00, e01);
                pB[jj] = pack_h2(e10, e11);
            }
            uint32_t af[4] = { pA[0], pB[0], pA[1], pB[1] };
            #pragma unroll
            for (int np=0; np<4; ++np) {
                uint32_t vh[4], vl[4];
                ldsm_x4(vh[0],vh[1],vh[2],vh[3], scvta(&Vth[np*16*QKS + g*16 + laneBv]));
                ldsm_x4(vl[0],vl[1],vl[2],vl[3], scvta(&Vtl[np*16*QKS + g*16 + laneBv]));
                #pragma unroll
                for (int s=0;s<2;s++) {
                    const int nd = np*2+s;
                    MMA_F16(o[nd], af, vh[s*2], vh[s*2+1]);
                    MMA_F16(o[nd], af, vl[s*2], vl[s*2+1]);
                }
            }
        }
        rs0 += __shfl_xor_sync(0xffffffffu, rs0, 1);
        rs0 += __shfl_xor_sync(0xffffffffu, rs0, 2);
        rs1 += __shfl_xor_sync(0xffffffffu, rs1, 1);
        rs1 += __shfl_xor_sync(0xffffffffu, rs1, 2);
        l0v = l0v*f0 + rs0;
        l1v = l1v*f1 + rs1;

        __syncthreads();
        if (t < 14) load_tile(t+2, t&1);
    }

    const float inv0 = 1.f / (l0v + EPSV);
    const float inv1 = 1.f / (l1v + EPSV);
    #pragma unroll
    for (int nd=0; nd<8; ++nd) {
        const int d = nd*8 + tig*2;
        const float2 vs = *(const float2*)&g_vsum[bh*HD + d];
        const float a0 = (o[nd][0] + EPSN*vs.x) * inv0;
        const float a1 = (o[nd][1] + EPSN*vs.y) * inv0;
        const float a2 = (o[nd][2] + EPSN*vs.x) * inv1;
        const float a3 = (o[nd][3] + EPSN*vs.y) * inv1;
        const size_t base0 = ((size_t)(b_*NSEQ + qg0))*DM + hh*HD + d;
        const size_t base1 = ((size_t)(b_*NSEQ + qg1))*DM + hh*HD + d;
        *(uint32_t*)&g_Th16[base0] = pack_h2(a0, a1);
        *(uint32_t*)&g_Th16[base1] = pack_h2(a2, a3);
    }
}

// ---------------------------------------------------------------------------
extern "C" void kernel_launch(void* const* d_in, const int* in_sizes, int n_in,
                              void* d_out, int out_size)
{
    const float* x      = (const float*)d_in[0];
    const float* policy = (const float*)d_in[1];
    const float* qkv_w  = (const float*)d_in[2];
    const float* qkv_b  = (const float*)d_in[3];
    const float* proj_w = (const float*)d_in[4];
    const float* proj_b = (const float*)d_in[5];
    const float* rph    = (const float*)d_in[6];
    const float* rpw    = (const float*)d_in[7];
    float* out = (float*)d_out;

    cudaFuncSetAttribute(flash_mma,
        cudaFuncAttributeMaxDynamicSharedMemorySize, FL_SMEM_BYTES);
    cudaFuncSetAttribute(gemm_mma,
        cudaFuncAttributeMaxDynamicSharedMemorySize, GEMM_SMEM_BYTES);

    const int n4x = NB*NSEQ*DM/4, n4q = 2304*DM/4, n4p = DM*DM/4;
    split_kernel<<<(n4x+255)/256,256>>>(x,      0, n4x);
    split_kernel<<<(n4q+255)/256,256>>>(qkv_w,  1, n4q);
    split_kernel<<<(n4p+255)/256,256>>>(proj_w, 2, n4p);

    gemm_mma<<<dim3(18,64),256,GEMM_SMEM_BYTES>>>(qkv_b, nullptr, 0);
    vtrans_kernel<<<dim3(16,NBH),256>>>();
    rel_kernel<<<NBH*256,256>>>(rph, rpw);
    vsum_kernel<<<NBH,256>>>();
    flash_mma<<<dim3(8,NBH),256,FL_SMEM_BYTES>>>(policy);
    gemm_mma<<<dim3(6,64),256,GEMM_SMEM_BYTES>>>(proj_b, out, 1);
}